// round 6
// baseline (speedup 1.0000x reference)
#include <cuda_runtime.h>
#include <cuda_fp16.h>

// ---------------------------------------------------------------- constants
#define NB_   512      // B*C batch slices
#define HW_   2304     // H*W
#define JJ_   110592   // D*H*W
#define RS_   32
#define RSQ_  1024
#define OUT_  1024
#define BB_   16
#define KK_   32768    // C*R*R

#define KS_   16               // K splits
#define KPC_  (JJ_ / KS_)      // 6912 per CTA
#define TILES_ (KPC_ / 64)     // 108 tiles of 64

#define KCP_  64               // proj k-chunks
#define KCLP_ (KK_ / KCP_)     // 512

// ---------------------------------------------------------------- scratch
__device__ float g_T  [HW_ * RS_];               // t[p][r]
__device__ float g_Ttr[RS_ * (size_t)JJ_];       // Tt transposed: [r][j]
__device__ float g_Gp [KS_ * (size_t)NB_ * RSQ_];// Gram partials
__device__ float g_G  [NB_ * RSQ_];              // Gram results
__device__ float g_part[KCP_ * BB_ * OUT_];      // projection partials

// ---------------------------------------------------------------- helpers
__device__ __forceinline__ unsigned pack_bf16x2(float hi, float lo) {
    unsigned r;
    asm("cvt.rn.bf16x2.f32 %0, %1, %2;" : "=r"(r) : "f"(hi), "f"(lo));
    return r;
}

__device__ __forceinline__ void cp16(void* sdst, const void* gsrc) {
    unsigned s = (unsigned)__cvta_generic_to_shared(sdst);
    asm volatile("cp.async.cg.shared.global [%0], [%1], 16;" :: "r"(s), "l"(gsrc));
}

// bf16 inputs, fp32 accumulate
#define MMA(D, A, B) \
    asm volatile("mma.sync.aligned.m16n8k16.row.col.f32.bf16.bf16.f32 " \
                 "{%0,%1,%2,%3}, {%4,%5,%6,%7}, {%8,%9}, {%0,%1,%2,%3};" \
                 : "+f"((D)[0]), "+f"((D)[1]), "+f"((D)[2]), "+f"((D)[3]) \
                 : "r"((A)[0]), "r"((A)[1]), "r"((A)[2]), "r"((A)[3]), \
                   "r"((B)[0]), "r"((B)[1]))

// ---------------------------------------------------------------- prep
// t[p,r] = sum_s core2[r,h,s] * core3[s,w,0]
__global__ void k_t(const float* __restrict__ core2, const float* __restrict__ core3) {
    int idx = blockIdx.x * blockDim.x + threadIdx.x;
    if (idx >= HW_ * RS_) return;
    int r = idx & 31;
    int p = idx >> 5;
    int h = p / 48, w = p % 48;
    const float* c2 = core2 + (r * 48 + h) * 32;
    float s = 0.f;
#pragma unroll
    for (int si = 0; si < 32; si++) s += c2[si] * core3[si * 48 + w];
    g_T[p * 32 + r] = s;
}

// Ttr[r][j] = core1[d,r] * t[p,r],  j = d*HW + p
__global__ void k_ttr(const float* __restrict__ core1) {
    int j = blockIdx.x * 256 + threadIdx.x;
    int r = blockIdx.y;
    int d = j / HW_;
    int p = j - d * HW_;
    g_Ttr[(size_t)r * JJ_ + j] = core1[d * 32 + r] * g_T[p * 32 + r];
}

// ---------------------------------------------------------------- gram (mma.sync)
// V[k,r] = x[k]*Tt[k,r]; G = V^T V. bf16 split V = Vh + Vl (bit-truncation hi).
// G ~= Vh^T Vh + Vh^T Vl + Vl^T Vh, all accumulated into 6 upper m16n8 tiles,
// lower triangle mirrored at writeout (sum of three terms is symmetric).
__global__ void __launch_bounds__(256, 3) k_gram(const float* __restrict__ x) {
    __shared__ float sTt[4][32][72];   // stride 72: conflict-free LDS.64
    __shared__ float sX [4][8][64];

    int tid = threadIdx.x;
    int w   = tid >> 5;
    int l   = tid & 31;
    int n0  = blockIdx.x * 8;
    int ks  = blockIdx.y;
    size_t j0 = (size_t)ks * KPC_;

    int g   = l >> 2;          // row group 0..7
    int tg2 = (l & 3) * 2;     // col pair base

    float acc[6][4];
#pragma unroll
    for (int i = 0; i < 6; i++)
#pragma unroll
        for (int j = 0; j < 4; j++) acc[i][j] = 0.f;

    auto issue = [&](int t, int b) {
        size_t jt = j0 + (size_t)t * 64;
        for (int idx = tid; idx < 512; idx += 256) {
            int row = idx >> 4, ch = idx & 15;
            cp16(&sTt[b][row][ch * 4], g_Ttr + (size_t)row * JJ_ + jt + ch * 4);
        }
        if (tid < 128) {
            int row = tid >> 4, ch = tid & 15;
            cp16(&sX[b][row][ch * 4], x + (size_t)(n0 + row) * JJ_ + jt + ch * 4);
        }
        asm volatile("cp.async.commit_group;" ::: "memory");
    };

    issue(0, 0);
    issue(1, 1);

    for (int t = 0; t < TILES_; t++) {
        int b = t & 3;
        if (t + 2 < TILES_) issue(t + 2, (t + 2) & 3);
        else asm volatile("cp.async.commit_group;" ::: "memory");
        asm volatile("cp.async.wait_group 2;" ::: "memory");
        __syncthreads();

#pragma unroll
        for (int kk = 0; kk < 4; kk++) {
            int kb = kk * 16;
            float2 xA = *(const float2*)&sX[b][w][kb + tg2];
            float2 xB = *(const float2*)&sX[b][w][kb + tg2 + 8];

            unsigned ah[2][4], al[2][4];
#pragma unroll
            for (int rr = 0; rr < 4; rr++) {       // rows g, g+8, g+16, g+24
                int row = g + 8 * rr;
                float2 tA = *(const float2*)&sTt[b][row][kb + tg2];
                float2 tB = *(const float2*)&sTt[b][row][kb + tg2 + 8];
                float uA0 = xA.x * tA.x, uA1 = xA.y * tA.y;
                float uB0 = xB.x * tB.x, uB1 = xB.y * tB.y;
                unsigned axA = __float_as_uint(uA0), ayA = __float_as_uint(uA1);
                unsigned axB = __float_as_uint(uB0), ayB = __float_as_uint(uB1);
                unsigned hA = __byte_perm(axA, ayA, 0x7632);   // truncated bf16 pair
                unsigned hB = __byte_perm(axB, ayB, 0x7632);
                float lA0 = uA0 - __uint_as_float(axA & 0xffff0000u);
                float lA1 = uA1 - __uint_as_float(ayA & 0xffff0000u);
                float lB0 = uB0 - __uint_as_float(axB & 0xffff0000u);
                float lB1 = uB1 - __uint_as_float(ayB & 0xffff0000u);
                int mt = rr >> 1, rg = rr & 1;
                ah[mt][rg]     = hA;
                ah[mt][rg + 2] = hB;
                al[mt][rg]     = pack_bf16x2(lA1, lA0);
                al[mt][rg + 2] = pack_bf16x2(lB1, lB0);
            }
            // B fragments are register subsets of A fragments (Gram property)
            unsigned bh[4][2] = {{ah[0][0], ah[0][2]}, {ah[0][1], ah[0][3]},
                                 {ah[1][0], ah[1][2]}, {ah[1][1], ah[1][3]}};
            unsigned bl[4][2] = {{al[0][0], al[0][2]}, {al[0][1], al[0][3]},
                                 {al[1][0], al[1][2]}, {al[1][1], al[1][3]}};

            // hh first (depends only on short-chain hi frags)
            MMA(acc[0], ah[0], bh[0]);
            MMA(acc[1], ah[0], bh[1]);
            MMA(acc[2], ah[0], bh[2]);
            MMA(acc[3], ah[0], bh[3]);
            MMA(acc[4], ah[1], bh[2]);
            MMA(acc[5], ah[1], bh[3]);
            // cross terms (lo frags have the trailing cvt in their chain)
            MMA(acc[0], ah[0], bl[0]); MMA(acc[0], al[0], bh[0]);
            MMA(acc[1], ah[0], bl[1]); MMA(acc[1], al[0], bh[1]);
            MMA(acc[2], ah[0], bl[2]); MMA(acc[2], al[0], bh[2]);
            MMA(acc[3], ah[0], bl[3]); MMA(acc[3], al[0], bh[3]);
            MMA(acc[4], ah[1], bl[2]); MMA(acc[4], al[1], bh[2]);
            MMA(acc[5], ah[1], bl[3]); MMA(acc[5], al[1], bh[3]);
        }
        __syncthreads();
    }

    // --- writeout partial Gram (mirror upper-right tiles to lower-left)
    float* P = g_Gp + ((size_t)ks * NB_ + n0 + w) * RSQ_;
    const int mt_of[6] = {0, 0, 0, 0, 1, 1};
    const int nt_of[6] = {0, 1, 2, 3, 2, 3};
#pragma unroll
    for (int ti = 0; ti < 6; ti++) {
        int r0 = mt_of[ti] * 16 + g;
        int r1 = r0 + 8;
        int q  = nt_of[ti] * 8 + tg2;
        P[r0 * 32 + q]     = acc[ti][0];
        P[r0 * 32 + q + 1] = acc[ti][1];
        P[r1 * 32 + q]     = acc[ti][2];
        P[r1 * 32 + q + 1] = acc[ti][3];
        if (ti == 2 || ti == 3) {
            P[q * 32 + r0]       = acc[ti][0];
            P[(q + 1) * 32 + r0] = acc[ti][1];
            P[q * 32 + r1]       = acc[ti][2];
            P[(q + 1) * 32 + r1] = acc[ti][3];
        }
    }
}

// sum K-split partials
__global__ void k_gsum() {
    int i = blockIdx.x * 256 + threadIdx.x;   // 512*1024 total
    float s = 0.f;
#pragma unroll
    for (int p = 0; p < KS_; p++)
        s += g_Gp[(size_t)p * NB_ * RSQ_ + i];
    g_G[i] = s;
}

// ---------------------------------------------------------------- projection
__global__ void __launch_bounds__(256) k_proj(const float* __restrict__ projw) {
    __shared__ float sw[64][33];
    __shared__ float sf[16][33];
    int ot  = blockIdx.x;
    int kc  = blockIdx.y;
    int tid = threadIdx.x;
    int o0  = ot * 64;
    int b   = tid >> 4;
    int oo  = tid & 15;

    float acc[4] = {0.f, 0.f, 0.f, 0.f};

    for (int kt = 0; kt < KCLP_; kt += 32) {
        int kbase = kc * KCLP_ + kt;
        {
            int orow = tid >> 2;
            int part = tid & 3;
            const float4* src = (const float4*)(projw + (size_t)(o0 + orow) * KK_ + kbase + part * 8);
            float4 v0 = src[0], v1 = src[1];
            float* drow = &sw[orow][part * 8];
            drow[0] = v0.x; drow[1] = v0.y; drow[2] = v0.z; drow[3] = v0.w;
            drow[4] = v1.x; drow[5] = v1.y; drow[6] = v1.z; drow[7] = v1.w;
        }
        {
            int frow = tid >> 4;
            int fcol = (tid & 15) * 2;
            float2 v = *(const float2*)(g_G + (size_t)frow * KK_ + kbase + fcol);
            sf[frow][fcol]     = v.x;
            sf[frow][fcol + 1] = v.y;
        }
        __syncthreads();
#pragma unroll
        for (int k = 0; k < 32; k++) {
            float fv = sf[b][k];
            acc[0] += fv * sw[oo * 4 + 0][k];
            acc[1] += fv * sw[oo * 4 + 1][k];
            acc[2] += fv * sw[oo * 4 + 2][k];
            acc[3] += fv * sw[oo * 4 + 3][k];
        }
        __syncthreads();
    }
#pragma unroll
    for (int j = 0; j < 4; j++)
        g_part[(size_t)kc * (BB_ * OUT_) + b * OUT_ + o0 + oo * 4 + j] = acc[j];
}

__global__ void k_final(const float* __restrict__ projb, float* __restrict__ out) {
    int idx = blockIdx.x * blockDim.x + threadIdx.x;
    if (idx >= BB_ * OUT_) return;
    float s = projb[idx & (OUT_ - 1)];
#pragma unroll
    for (int kc = 0; kc < KCP_; kc++) s += g_part[kc * (BB_ * OUT_) + idx];
    out[idx] = s;
}

// ---------------------------------------------------------------- launch
extern "C" void kernel_launch(void* const* d_in, const int* in_sizes, int n_in,
                              void* d_out, int out_size) {
    const float* x     = (const float*)d_in[0];
    const float* core1 = (const float*)d_in[1];
    const float* core2 = (const float*)d_in[2];
    const float* core3 = (const float*)d_in[3];
    const float* projw = (const float*)d_in[4];
    const float* projb = (const float*)d_in[5];
    float* out = (float*)d_out;

    k_t<<<(HW_ * RS_ + 255) / 256, 256>>>(core2, core3);
    dim3 tg(JJ_ / 256, RS_);
    k_ttr<<<tg, 256>>>(core1);
    dim3 gg(NB_ / 8, KS_);
    k_gram<<<gg, 256>>>(x);
    k_gsum<<<(NB_ * RSQ_) / 256, 256>>>();
    dim3 pg(16, KCP_);
    k_proj<<<pg, 256>>>(projw);
    k_final<<<(BB_ * OUT_ + 255) / 256, 256>>>(projb, out);
}

// round 7
// speedup vs baseline: 1.0499x; 1.0499x over previous
#include <cuda_runtime.h>
#include <cuda_fp16.h>

// ---------------------------------------------------------------- constants
#define NB_   512      // B*C batch slices
#define HW_   2304     // H*W
#define JJ_   110592   // D*H*W
#define RS_   32
#define RSQ_  1024
#define OUT_  1024
#define BB_   16
#define KK_   32768    // C*R*R

#define KS_   32               // K splits
#define KPC_  (JJ_ / KS_)      // 3456 per CTA
#define TILES_ (KPC_ / 64)     // 54 tiles of 64

#define KCP_  64               // proj k-chunks
#define KCLP_ (KK_ / KCP_)     // 512

#define LSCALE_   4096.0f

// ---------------------------------------------------------------- scratch
__device__ float g_T  [HW_ * RS_];               // t[p][r]
__device__ float g_Ttr[RS_ * (size_t)JJ_];       // Tt transposed: [r][j]
__device__ float g_Gp [KS_ * (size_t)NB_ * RSQ_];// Gram partials
__device__ float g_G  [NB_ * RSQ_];              // Gram results
__device__ float g_part[KCP_ * BB_ * OUT_];      // projection partials

// ---------------------------------------------------------------- helpers
__device__ __forceinline__ void cp16(void* sdst, const void* gsrc) {
    unsigned s = (unsigned)__cvta_generic_to_shared(sdst);
    asm volatile("cp.async.cg.shared.global [%0], [%1], 16;" :: "r"(s), "l"(gsrc));
}

// fp16 inputs, fp32 accumulate
#define MMAF(D, A, B) \
    asm volatile("mma.sync.aligned.m16n8k16.row.col.f32.f16.f16.f32 " \
                 "{%0,%1,%2,%3}, {%4,%5,%6,%7}, {%8,%9}, {%0,%1,%2,%3};" \
                 : "+f"((D)[0]), "+f"((D)[1]), "+f"((D)[2]), "+f"((D)[3]) \
                 : "r"((A)[0]), "r"((A)[1]), "r"((A)[2]), "r"((A)[3]), \
                   "r"((B)[0]), "r"((B)[1]))

// fp16 inputs, fp16 accumulate (2 f16x2 D regs)
#define MMAH(D, A, B) \
    asm volatile("mma.sync.aligned.m16n8k16.row.col.f16.f16.f16.f16 " \
                 "{%0,%1}, {%2,%3,%4,%5}, {%6,%7}, {%0,%1};" \
                 : "+r"((D)[0]), "+r"((D)[1]) \
                 : "r"((A)[0]), "r"((A)[1]), "r"((A)[2]), "r"((A)[3]), \
                   "r"((B)[0]), "r"((B)[1]))

// ---------------------------------------------------------------- prep
// t[p,r] = sum_s core2[r,h,s] * core3[s,w,0]
__global__ void k_t(const float* __restrict__ core2, const float* __restrict__ core3) {
    int idx = blockIdx.x * blockDim.x + threadIdx.x;
    if (idx >= HW_ * RS_) return;
    int r = idx & 31;
    int p = idx >> 5;
    int h = p / 48, w = p % 48;
    const float* c2 = core2 + (r * 48 + h) * 32;
    float s = 0.f;
#pragma unroll
    for (int si = 0; si < 32; si++) s += c2[si] * core3[si * 48 + w];
    g_T[p * 32 + r] = s;
}

// Ttr[r][j] = core1[d,r] * t[p,r],  j = d*HW + p
__global__ void k_ttr(const float* __restrict__ core1) {
    int j = blockIdx.x * 256 + threadIdx.x;
    int r = blockIdx.y;
    int d = j / HW_;
    int p = j - d * HW_;
    g_Ttr[(size_t)r * JJ_ + j] = core1[d * 32 + r] * g_T[p * 32 + r];
}

// ---------------------------------------------------------------- gram (mma.sync)
// V[k,r] = x[k]*Tt[k,r]; G = V^T V.  fp16 split V = Vh + Vl/4096 (+eps).
// G ~= Vh^T Vh  (6 upper m16n8 tiles, fp32 acc)
//    + C + C^T, C = Vh^T (Vl*4096)   (8 full tiles, fp16 acc, rescaled at writeout)
__global__ void __launch_bounds__(256, 3) k_gram(const float* __restrict__ x) {
    __shared__ float sTt[4][32][72];   // stride 72: conflict-free LDS.64; reused for C transpose
    __shared__ float sX [4][8][64];

    int tid = threadIdx.x;
    int w   = tid >> 5;
    int l   = tid & 31;
    int n0  = blockIdx.x * 8;
    int ks  = blockIdx.y;
    size_t j0 = (size_t)ks * KPC_;

    int g   = l >> 2;          // row group 0..7
    int tg2 = (l & 3) * 2;     // col pair base

    float acc[6][4];
#pragma unroll
    for (int i = 0; i < 6; i++)
#pragma unroll
        for (int j = 0; j < 4; j++) acc[i][j] = 0.f;
    unsigned accc[8][2];
#pragma unroll
    for (int i = 0; i < 8; i++) { accc[i][0] = 0u; accc[i][1] = 0u; }

    auto issue = [&](int t, int b) {
        size_t jt = j0 + (size_t)t * 64;
        for (int idx = tid; idx < 512; idx += 256) {
            int row = idx >> 4, ch = idx & 15;
            cp16(&sTt[b][row][ch * 4], g_Ttr + (size_t)row * JJ_ + jt + ch * 4);
        }
        if (tid < 128) {
            int row = tid >> 4, ch = tid & 15;
            cp16(&sX[b][row][ch * 4], x + (size_t)(n0 + row) * JJ_ + jt + ch * 4);
        }
        asm volatile("cp.async.commit_group;" ::: "memory");
    };

    issue(0, 0);
    issue(1, 1);

    for (int t = 0; t < TILES_; t++) {
        int b = t & 3;
        if (t + 2 < TILES_) issue(t + 2, (t + 2) & 3);
        else asm volatile("cp.async.commit_group;" ::: "memory");
        asm volatile("cp.async.wait_group 2;" ::: "memory");
        __syncthreads();

#pragma unroll
        for (int kk = 0; kk < 4; kk++) {
            int kb = kk * 16;
            float2 xA = *(const float2*)&sX[b][w][kb + tg2];
            float2 xB = *(const float2*)&sX[b][w][kb + tg2 + 8];

            unsigned ah[2][4], al[2][4];
#pragma unroll
            for (int rr = 0; rr < 4; rr++) {       // rows g, g+8, g+16, g+24
                int row = g + 8 * rr;
                float2 tA = *(const float2*)&sTt[b][row][kb + tg2];
                float2 tB = *(const float2*)&sTt[b][row][kb + tg2 + 8];
                float uA0 = xA.x * tA.x, uA1 = xA.y * tA.y;
                float uB0 = xB.x * tB.x, uB1 = xB.y * tB.y;
                __half2 hA = __floats2half2_rn(uA0, uA1);   // low = even k
                __half2 hB = __floats2half2_rn(uB0, uB1);
                float2 fA = __half22float2(hA);
                float2 fB = __half22float2(hB);
                __half2 lA = __floats2half2_rn((uA0 - fA.x) * LSCALE_, (uA1 - fA.y) * LSCALE_);
                __half2 lB = __floats2half2_rn((uB0 - fB.x) * LSCALE_, (uB1 - fB.y) * LSCALE_);
                int mt = rr >> 1, rg = rr & 1;
                ah[mt][rg]     = *reinterpret_cast<unsigned*>(&hA);
                ah[mt][rg + 2] = *reinterpret_cast<unsigned*>(&hB);
                al[mt][rg]     = *reinterpret_cast<unsigned*>(&lA);
                al[mt][rg + 2] = *reinterpret_cast<unsigned*>(&lB);
            }
            // B fragments are register subsets of A fragments (Gram property)
            unsigned bh[4][2] = {{ah[0][0], ah[0][2]}, {ah[0][1], ah[0][3]},
                                 {ah[1][0], ah[1][2]}, {ah[1][1], ah[1][3]}};
            unsigned bl[4][2] = {{al[0][0], al[0][2]}, {al[0][1], al[0][3]},
                                 {al[1][0], al[1][2]}, {al[1][1], al[1][3]}};

            // hh upper tiles: (0,0)(0,1)(0,2)(0,3)(1,2)(1,3); (1,0)(1,1) mirror of (0,2)(0,3)
            MMAF(acc[0], ah[0], bh[0]);
            MMAF(acc[1], ah[0], bh[1]);
            MMAF(acc[2], ah[0], bh[2]);
            MMAF(acc[3], ah[0], bh[3]);
            MMAF(acc[4], ah[1], bh[2]);
            MMAF(acc[5], ah[1], bh[3]);
            // C = Vh^T Vl : all 8 tiles, fp16 accumulate
            MMAH(accc[0], ah[0], bl[0]);
            MMAH(accc[1], ah[0], bl[1]);
            MMAH(accc[2], ah[0], bl[2]);
            MMAH(accc[3], ah[0], bl[3]);
            MMAH(accc[4], ah[1], bl[0]);
            MMAH(accc[5], ah[1], bl[1]);
            MMAH(accc[6], ah[1], bl[2]);
            MMAH(accc[7], ah[1], bl[3]);
        }
        __syncthreads();
    }

    // ---- stage C into smem (per-warp 32x33 slab, reusing sTt memory) ----
    __syncthreads();                       // everyone done reading sTt/sX
    float* Cs = (float*)sTt + w * (32 * 33);
#pragma unroll
    for (int ti = 0; ti < 8; ti++) {
        int mt = ti >> 2, nt = ti & 3;
        int r0 = mt * 16 + g, r1 = r0 + 8;
        int q  = nt * 8 + tg2;
        float2 v0 = __half22float2(*reinterpret_cast<__half2*>(&accc[ti][0]));
        float2 v1 = __half22float2(*reinterpret_cast<__half2*>(&accc[ti][1]));
        Cs[r0 * 33 + q]     = v0.x;
        Cs[r0 * 33 + q + 1] = v0.y;
        Cs[r1 * 33 + q]     = v1.x;
        Cs[r1 * 33 + q + 1] = v1.y;
    }
    __syncwarp();

    // ---- writeout: G = hh + (C + C^T) / LSCALE ----
    const float cs = 1.0f / LSCALE_;
    float* P = g_Gp + ((size_t)ks * NB_ + n0 + w) * RSQ_;
    const int mt_of[6] = {0, 0, 0, 0, 1, 1};
    const int nt_of[6] = {0, 1, 2, 3, 2, 3};
#pragma unroll
    for (int ti = 0; ti < 6; ti++) {
        int r0 = mt_of[ti] * 16 + g;
        int r1 = r0 + 8;
        int q  = nt_of[ti] * 8 + tg2;
        float v00 = acc[ti][0] + (Cs[r0 * 33 + q]     + Cs[q * 33 + r0])       * cs;
        float v01 = acc[ti][1] + (Cs[r0 * 33 + q + 1] + Cs[(q + 1) * 33 + r0]) * cs;
        float v10 = acc[ti][2] + (Cs[r1 * 33 + q]     + Cs[q * 33 + r1])       * cs;
        float v11 = acc[ti][3] + (Cs[r1 * 33 + q + 1] + Cs[(q + 1) * 33 + r1]) * cs;
        P[r0 * 32 + q]     = v00;
        P[r0 * 32 + q + 1] = v01;
        P[r1 * 32 + q]     = v10;
        P[r1 * 32 + q + 1] = v11;
        if (ti == 2 || ti == 3) {      // mirror upper-right -> lower-left
            P[q * 32 + r0]       = v00;
            P[(q + 1) * 32 + r0] = v01;
            P[q * 32 + r1]       = v10;
            P[(q + 1) * 32 + r1] = v11;
        }
    }
}

// sum K-split partials (float4 per thread)
__global__ void k_gsum() {
    int i4 = blockIdx.x * 256 + threadIdx.x;   // over 512*1024/4 float4s
    float4 s = {0.f, 0.f, 0.f, 0.f};
#pragma unroll
    for (int p = 0; p < KS_; p++) {
        float4 v = *((const float4*)(g_Gp + (size_t)p * NB_ * RSQ_) + i4);
        s.x += v.x; s.y += v.y; s.z += v.z; s.w += v.w;
    }
    *((float4*)g_G + i4) = s;
}

// ---------------------------------------------------------------- projection
__global__ void __launch_bounds__(256) k_proj(const float* __restrict__ projw) {
    __shared__ float sw[64][33];
    __shared__ float sf[16][33];
    int ot  = blockIdx.x;
    int kc  = blockIdx.y;
    int tid = threadIdx.x;
    int o0  = ot * 64;
    int b   = tid >> 4;
    int oo  = tid & 15;

    float acc[4] = {0.f, 0.f, 0.f, 0.f};

    for (int kt = 0; kt < KCLP_; kt += 32) {
        int kbase = kc * KCLP_ + kt;
        {
            int orow = tid >> 2;
            int part = tid & 3;
            const float4* src = (const float4*)(projw + (size_t)(o0 + orow) * KK_ + kbase + part * 8);
            float4 v0 = src[0], v1 = src[1];
            float* drow = &sw[orow][part * 8];
            drow[0] = v0.x; drow[1] = v0.y; drow[2] = v0.z; drow[3] = v0.w;
            drow[4] = v1.x; drow[5] = v1.y; drow[6] = v1.z; drow[7] = v1.w;
        }
        {
            int frow = tid >> 4;
            int fcol = (tid & 15) * 2;
            float2 v = *(const float2*)(g_G + (size_t)frow * KK_ + kbase + fcol);
            sf[frow][fcol]     = v.x;
            sf[frow][fcol + 1] = v.y;
        }
        __syncthreads();
#pragma unroll
        for (int k = 0; k < 32; k++) {
            float fv = sf[b][k];
            acc[0] += fv * sw[oo * 4 + 0][k];
            acc[1] += fv * sw[oo * 4 + 1][k];
            acc[2] += fv * sw[oo * 4 + 2][k];
            acc[3] += fv * sw[oo * 4 + 3][k];
        }
        __syncthreads();
    }
#pragma unroll
    for (int j = 0; j < 4; j++)
        g_part[(size_t)kc * (BB_ * OUT_) + b * OUT_ + o0 + oo * 4 + j] = acc[j];
}

__global__ void k_final(const float* __restrict__ projb, float* __restrict__ out) {
    int idx = blockIdx.x * blockDim.x + threadIdx.x;
    if (idx >= BB_ * OUT_) return;
    float s = projb[idx & (OUT_ - 1)];
#pragma unroll
    for (int kc = 0; kc < KCP_; kc++) s += g_part[kc * (BB_ * OUT_) + idx];
    out[idx] = s;
}

// ---------------------------------------------------------------- launch
extern "C" void kernel_launch(void* const* d_in, const int* in_sizes, int n_in,
                              void* d_out, int out_size) {
    const float* x     = (const float*)d_in[0];
    const float* core1 = (const float*)d_in[1];
    const float* core2 = (const float*)d_in[2];
    const float* core3 = (const float*)d_in[3];
    const float* projw = (const float*)d_in[4];
    const float* projb = (const float*)d_in[5];
    float* out = (float*)d_out;

    k_t<<<(HW_ * RS_ + 255) / 256, 256>>>(core2, core3);
    dim3 tg(JJ_ / 256, RS_);
    k_ttr<<<tg, 256>>>(core1);
    dim3 gg(NB_ / 8, KS_);
    k_gram<<<gg, 256>>>(x);
    k_gsum<<<(NB_ * RSQ_) / 1024, 256>>>();
    dim3 pg(16, KCP_);
    k_proj<<<pg, 256>>>(projw);
    k_final<<<(BB_ * OUT_ + 255) / 256, 256>>>(projb, out);
}

// round 8
// speedup vs baseline: 1.8968x; 1.8066x over previous
#include <cuda_runtime.h>
#include <cuda_fp16.h>

// ---------------------------------------------------------------- constants
#define NB_   512      // B*C batch slices
#define HW_   2304     // H*W
#define JJ_   110592   // D*H*W
#define RS_   32
#define RSQ_  1024
#define OUT_  1024
#define BB_   16
#define KK_   32768    // C*R*R

#define KS_   32               // K splits
#define KPC_  (JJ_ / KS_)      // 3456 per CTA
#define TILES_ (KPC_ / 64)     // 54 tiles of 64

#define KCP_  64               // proj k-chunks
#define KCLP_ (KK_ / KCP_)     // 512

// ---------------------------------------------------------------- scratch
__device__ float g_T  [HW_ * RS_];               // t[p][r]
__device__ float g_Ttr[RS_ * (size_t)JJ_];       // Tt transposed: [r][j]
__device__ float g_Gp [KS_ * (size_t)NB_ * RSQ_];// Gram partials
__device__ float g_G  [NB_ * RSQ_];              // Gram results
__device__ float g_part[KCP_ * BB_ * OUT_];      // projection partials

// ---------------------------------------------------------------- helpers
__device__ __forceinline__ void cp16(void* sdst, const void* gsrc) {
    unsigned s = (unsigned)__cvta_generic_to_shared(sdst);
    asm volatile("cp.async.cg.shared.global [%0], [%1], 16;" :: "r"(s), "l"(gsrc));
}

// fp16 inputs, fp32 accumulate
#define MMAF(D, A, B) \
    asm volatile("mma.sync.aligned.m16n8k16.row.col.f32.f16.f16.f32 " \
                 "{%0,%1,%2,%3}, {%4,%5,%6,%7}, {%8,%9}, {%0,%1,%2,%3};" \
                 : "+f"((D)[0]), "+f"((D)[1]), "+f"((D)[2]), "+f"((D)[3]) \
                 : "r"((A)[0]), "r"((A)[1]), "r"((A)[2]), "r"((A)[3]), \
                   "r"((B)[0]), "r"((B)[1]))

// ---------------------------------------------------------------- prep
// t[p,r] = sum_s core2[r,h,s] * core3[s,w,0]
__global__ void k_t(const float* __restrict__ core2, const float* __restrict__ core3) {
    int idx = blockIdx.x * blockDim.x + threadIdx.x;
    if (idx >= HW_ * RS_) return;
    int r = idx & 31;
    int p = idx >> 5;
    int h = p / 48, w = p % 48;
    const float* c2 = core2 + (r * 48 + h) * 32;
    float s = 0.f;
#pragma unroll
    for (int si = 0; si < 32; si++) s += c2[si] * core3[si * 48 + w];
    g_T[p * 32 + r] = s;
}

// Ttr[r][j] = core1[d,r] * t[p,r],  j = d*HW + p
__global__ void k_ttr(const float* __restrict__ core1) {
    int j = blockIdx.x * 256 + threadIdx.x;
    int r = blockIdx.y;
    int d = j / HW_;
    int p = j - d * HW_;
    g_Ttr[(size_t)r * JJ_ + j] = core1[d * 32 + r] * g_T[p * 32 + r];
}

// ---------------------------------------------------------------- gram (mma.sync)
// V[k,r] = x[k]*Tt[k,r]; G = V^T V, V rounded to fp16 (RN -> unbiased, errors
// average out over 110592 k-terms). 6 upper m16n8 tiles, fp32 accumulate;
// lower triangle mirrored at writeout.
__global__ void __launch_bounds__(256, 4) k_gram(const float* __restrict__ x) {
    __shared__ float sTt[4][32][72];   // stride 72: conflict-free LDS.64
    __shared__ float sX [4][8][64];

    int tid = threadIdx.x;
    int w   = tid >> 5;
    int l   = tid & 31;
    int n0  = blockIdx.x * 8;
    int ks  = blockIdx.y;
    size_t j0 = (size_t)ks * KPC_;

    int g   = l >> 2;          // row group 0..7
    int tg2 = (l & 3) * 2;     // col pair base

    float acc[6][4];
#pragma unroll
    for (int i = 0; i < 6; i++)
#pragma unroll
        for (int j = 0; j < 4; j++) acc[i][j] = 0.f;

    auto issue = [&](int t, int b) {
        size_t jt = j0 + (size_t)t * 64;
        for (int idx = tid; idx < 512; idx += 256) {
            int row = idx >> 4, ch = idx & 15;
            cp16(&sTt[b][row][ch * 4], g_Ttr + (size_t)row * JJ_ + jt + ch * 4);
        }
        if (tid < 128) {
            int row = tid >> 4, ch = tid & 15;
            cp16(&sX[b][row][ch * 4], x + (size_t)(n0 + row) * JJ_ + jt + ch * 4);
        }
        asm volatile("cp.async.commit_group;" ::: "memory");
    };

    issue(0, 0);
    issue(1, 1);

    for (int t = 0; t < TILES_; t++) {
        int b = t & 3;
        if (t + 2 < TILES_) issue(t + 2, (t + 2) & 3);
        else asm volatile("cp.async.commit_group;" ::: "memory");
        asm volatile("cp.async.wait_group 2;" ::: "memory");
        __syncthreads();

#pragma unroll
        for (int kk = 0; kk < 4; kk++) {
            int kb = kk * 16;
            float2 xA = *(const float2*)&sX[b][w][kb + tg2];
            float2 xB = *(const float2*)&sX[b][w][kb + tg2 + 8];

            unsigned ah[2][4];
#pragma unroll
            for (int rr = 0; rr < 4; rr++) {       // rows g, g+8, g+16, g+24
                int row = g + 8 * rr;
                float2 tA = *(const float2*)&sTt[b][row][kb + tg2];
                float2 tB = *(const float2*)&sTt[b][row][kb + tg2 + 8];
                __half2 hA = __floats2half2_rn(xA.x * tA.x, xA.y * tA.y);  // low = even k
                __half2 hB = __floats2half2_rn(xB.x * tB.x, xB.y * tB.y);
                int mt = rr >> 1, rg = rr & 1;
                ah[mt][rg]     = *reinterpret_cast<unsigned*>(&hA);
                ah[mt][rg + 2] = *reinterpret_cast<unsigned*>(&hB);
            }
            // B fragments are register subsets of A fragments (Gram property)
            unsigned bh[4][2] = {{ah[0][0], ah[0][2]}, {ah[0][1], ah[0][3]},
                                 {ah[1][0], ah[1][2]}, {ah[1][1], ah[1][3]}};

            // upper tiles: (0,0)(0,1)(0,2)(0,3)(1,2)(1,3); (1,0)(1,1) mirror of (0,2)(0,3)
            MMAF(acc[0], ah[0], bh[0]);
            MMAF(acc[1], ah[0], bh[1]);
            MMAF(acc[2], ah[0], bh[2]);
            MMAF(acc[3], ah[0], bh[3]);
            MMAF(acc[4], ah[1], bh[2]);
            MMAF(acc[5], ah[1], bh[3]);
        }
        __syncthreads();
    }

    // --- writeout partial Gram (mirror upper-right tiles to lower-left)
    float* P = g_Gp + ((size_t)ks * NB_ + n0 + w) * RSQ_;
    const int mt_of[6] = {0, 0, 0, 0, 1, 1};
    const int nt_of[6] = {0, 1, 2, 3, 2, 3};
#pragma unroll
    for (int ti = 0; ti < 6; ti++) {
        int r0 = mt_of[ti] * 16 + g;
        int r1 = r0 + 8;
        int q  = nt_of[ti] * 8 + tg2;
        P[r0 * 32 + q]     = acc[ti][0];
        P[r0 * 32 + q + 1] = acc[ti][1];
        P[r1 * 32 + q]     = acc[ti][2];
        P[r1 * 32 + q + 1] = acc[ti][3];
        if (ti == 2 || ti == 3) {
            P[q * 32 + r0]       = acc[ti][0];
            P[(q + 1) * 32 + r0] = acc[ti][1];
            P[q * 32 + r1]       = acc[ti][2];
            P[(q + 1) * 32 + r1] = acc[ti][3];
        }
    }
}

// sum K-split partials (float4 per thread)
__global__ void k_gsum() {
    int i4 = blockIdx.x * 256 + threadIdx.x;   // over 512*1024/4 float4s
    float4 s = {0.f, 0.f, 0.f, 0.f};
#pragma unroll
    for (int p = 0; p < KS_; p++) {
        float4 v = *((const float4*)(g_Gp + (size_t)p * NB_ * RSQ_) + i4);
        s.x += v.x; s.y += v.y; s.z += v.z; s.w += v.w;
    }
    *((float4*)g_G + i4) = s;
}

// ---------------------------------------------------------------- projection
__global__ void __launch_bounds__(256) k_proj(const float* __restrict__ projw) {
    __shared__ float sw[64][33];
    __shared__ float sf[16][33];
    int ot  = blockIdx.x;
    int kc  = blockIdx.y;
    int tid = threadIdx.x;
    int o0  = ot * 64;
    int b   = tid >> 4;
    int oo  = tid & 15;

    float acc[4] = {0.f, 0.f, 0.f, 0.f};

    for (int kt = 0; kt < KCLP_; kt += 32) {
        int kbase = kc * KCLP_ + kt;
        {
            int orow = tid >> 2;
            int part = tid & 3;
            const float4* src = (const float4*)(projw + (size_t)(o0 + orow) * KK_ + kbase + part * 8);
            float4 v0 = src[0], v1 = src[1];
            float* drow = &sw[orow][part * 8];
            drow[0] = v0.x; drow[1] = v0.y; drow[2] = v0.z; drow[3] = v0.w;
            drow[4] = v1.x; drow[5] = v1.y; drow[6] = v1.z; drow[7] = v1.w;
        }
        {
            int frow = tid >> 4;
            int fcol = (tid & 15) * 2;
            float2 v = *(const float2*)(g_G + (size_t)frow * KK_ + kbase + fcol);
            sf[frow][fcol]     = v.x;
            sf[frow][fcol + 1] = v.y;
        }
        __syncthreads();
#pragma unroll
        for (int k = 0; k < 32; k++) {
            float fv = sf[b][k];
            acc[0] += fv * sw[oo * 4 + 0][k];
            acc[1] += fv * sw[oo * 4 + 1][k];
            acc[2] += fv * sw[oo * 4 + 2][k];
            acc[3] += fv * sw[oo * 4 + 3][k];
        }
        __syncthreads();
    }
#pragma unroll
    for (int j = 0; j < 4; j++)
        g_part[(size_t)kc * (BB_ * OUT_) + b * OUT_ + o0 + oo * 4 + j] = acc[j];
}

__global__ void k_final(const float* __restrict__ projb, float* __restrict__ out) {
    int idx = blockIdx.x * blockDim.x + threadIdx.x;
    if (idx >= BB_ * OUT_) return;
    float s = projb[idx & (OUT_ - 1)];
#pragma unroll
    for (int kc = 0; kc < KCP_; kc++) s += g_part[kc * (BB_ * OUT_) + idx];
    out[idx] = s;
}

// ---------------------------------------------------------------- launch
extern "C" void kernel_launch(void* const* d_in, const int* in_sizes, int n_in,
                              void* d_out, int out_size) {
    const float* x     = (const float*)d_in[0];
    const float* core1 = (const float*)d_in[1];
    const float* core2 = (const float*)d_in[2];
    const float* core3 = (const float*)d_in[3];
    const float* projw = (const float*)d_in[4];
    const float* projb = (const float*)d_in[5];
    float* out = (float*)d_out;

    k_t<<<(HW_ * RS_ + 255) / 256, 256>>>(core2, core3);
    dim3 tg(JJ_ / 256, RS_);
    k_ttr<<<tg, 256>>>(core1);
    dim3 gg(NB_ / 8, KS_);
    k_gram<<<gg, 256>>>(x);
    k_gsum<<<(NB_ * RSQ_) / 1024, 256>>>();
    dim3 pg(16, KCP_);
    k_proj<<<pg, 256>>>(projw);
    k_final<<<(BB_ * OUT_ + 255) / 256, 256>>>(projb, out);
}

// round 9
// speedup vs baseline: 2.2420x; 1.1820x over previous
#include <cuda_runtime.h>
#include <cuda_fp16.h>

// ---------------------------------------------------------------- constants
#define NB_   512      // B*C batch slices
#define HW_   2304     // H*W
#define JJ_   110592   // D*H*W
#define RS_   32
#define RSQ_  1024
#define OUT_  1024
#define BB_   16
#define KK_   32768    // C*R*R

#define KS_   32               // K splits
#define KPC_  (JJ_ / KS_)      // 3456 per CTA
#define TILES_ (KPC_ / 64)     // 54 tiles of 64

#define KCP_  64               // proj k-chunks
#define KCLP_ (KK_ / KCP_)     // 512

// ---------------------------------------------------------------- scratch
__device__ float  g_T  [HW_ * RS_];               // t[p][r]
__device__ __half g_Ttrh[RS_ * (size_t)JJ_];      // fp16 Tt transposed: [r][j]
__device__ float  g_Gp [KS_ * (size_t)NB_ * RSQ_];// Gram partials
__device__ float  g_G  [NB_ * RSQ_];              // Gram results
__device__ float  g_part[KCP_ * BB_ * OUT_];      // projection partials

// ---------------------------------------------------------------- helpers
__device__ __forceinline__ void cp16(void* sdst, const void* gsrc) {
    unsigned s = (unsigned)__cvta_generic_to_shared(sdst);
    asm volatile("cp.async.cg.shared.global [%0], [%1], 16;" :: "r"(s), "l"(gsrc));
}

// fp16 inputs, fp32 accumulate
#define MMAF(D, A, B) \
    asm volatile("mma.sync.aligned.m16n8k16.row.col.f32.f16.f16.f32 " \
                 "{%0,%1,%2,%3}, {%4,%5,%6,%7}, {%8,%9}, {%0,%1,%2,%3};" \
                 : "+f"((D)[0]), "+f"((D)[1]), "+f"((D)[2]), "+f"((D)[3]) \
                 : "r"((A)[0]), "r"((A)[1]), "r"((A)[2]), "r"((A)[3]), \
                   "r"((B)[0]), "r"((B)[1]))

// ---------------------------------------------------------------- prep
// t[p,r] = sum_s core2[r,h,s] * core3[s,w,0]
__global__ void k_t(const float* __restrict__ core2, const float* __restrict__ core3) {
    int idx = blockIdx.x * blockDim.x + threadIdx.x;
    if (idx >= HW_ * RS_) return;
    int r = idx & 31;
    int p = idx >> 5;
    int h = p / 48, w = p % 48;
    const float* c2 = core2 + (r * 48 + h) * 32;
    float s = 0.f;
#pragma unroll
    for (int si = 0; si < 32; si++) s += c2[si] * core3[si * 48 + w];
    g_T[p * 32 + r] = s;
}

// Ttrh[r][j] = fp16( core1[d,r] * t[p,r] ),  j = d*HW + p
__global__ void k_ttr(const float* __restrict__ core1) {
    int j = blockIdx.x * 256 + threadIdx.x;
    int r = blockIdx.y;
    int d = j / HW_;
    int p = j - d * HW_;
    g_Ttrh[(size_t)r * JJ_ + j] = __float2half_rn(core1[d * 32 + r] * g_T[p * 32 + r]);
}

// ---------------------------------------------------------------- gram (mma.sync)
// V[k,r] = fp16(x[k]) * fp16(Tt[k,r]) (HMUL2); G = V^T V.
// 6 upper m16n8 tiles, fp32 accumulate; lower triangle mirrored at writeout.
__global__ void __launch_bounds__(256, 4) k_gram(const float* __restrict__ x) {
    __shared__ __half sTt[4][32][72];  // stride 72 halves (144B): conflict-free LDS.32
    __shared__ float  sX [4][8][64];

    int tid = threadIdx.x;
    int w   = tid >> 5;
    int l   = tid & 31;
    int n0  = blockIdx.x * 8;
    int ks  = blockIdx.y;
    size_t j0 = (size_t)ks * KPC_;

    int g   = l >> 2;          // row group 0..7
    int tg2 = (l & 3) * 2;     // col pair base

    float acc[6][4];
#pragma unroll
    for (int i = 0; i < 6; i++)
#pragma unroll
        for (int j = 0; j < 4; j++) acc[i][j] = 0.f;

    auto issue = [&](int t, int b) {
        size_t jt = j0 + (size_t)t * 64;
        if (tid < 256) {   // 256 x 16B chunks: 32 rows x 8 chunks (fp16 row = 128B)
            int row = tid >> 3, ch = tid & 7;
            cp16(&sTt[b][row][ch * 8], g_Ttrh + (size_t)row * JJ_ + jt + ch * 8);
        }
        if (tid < 128) {
            int row = tid >> 4, ch = tid & 15;
            cp16(&sX[b][row][ch * 4], x + (size_t)(n0 + row) * JJ_ + jt + ch * 4);
        }
        asm volatile("cp.async.commit_group;" ::: "memory");
    };

    issue(0, 0);
    issue(1, 1);

    for (int t = 0; t < TILES_; t++) {
        int b = t & 3;
        if (t + 2 < TILES_) issue(t + 2, (t + 2) & 3);
        else asm volatile("cp.async.commit_group;" ::: "memory");
        asm volatile("cp.async.wait_group 2;" ::: "memory");
        __syncthreads();

#pragma unroll
        for (int kk = 0; kk < 4; kk++) {
            int kb = kk * 16;
            float2 xA = *(const float2*)&sX[b][w][kb + tg2];
            float2 xB = *(const float2*)&sX[b][w][kb + tg2 + 8];
            __half2 xhA = __floats2half2_rn(xA.x, xA.y);   // low = even k
            __half2 xhB = __floats2half2_rn(xB.x, xB.y);

            unsigned ah[2][4];
#pragma unroll
            for (int rr = 0; rr < 4; rr++) {       // rows g, g+8, g+16, g+24
                int row = g + 8 * rr;
                __half2 tA = *(const __half2*)&sTt[b][row][kb + tg2];
                __half2 tB = *(const __half2*)&sTt[b][row][kb + tg2 + 8];
                __half2 hA = __hmul2(xhA, tA);
                __half2 hB = __hmul2(xhB, tB);
                int mt = rr >> 1, rg = rr & 1;
                ah[mt][rg]     = *reinterpret_cast<unsigned*>(&hA);
                ah[mt][rg + 2] = *reinterpret_cast<unsigned*>(&hB);
            }
            // B fragments are register subsets of A fragments (Gram property)
            unsigned bh[4][2] = {{ah[0][0], ah[0][2]}, {ah[0][1], ah[0][3]},
                                 {ah[1][0], ah[1][2]}, {ah[1][1], ah[1][3]}};

            // upper tiles: (0,0)(0,1)(0,2)(0,3)(1,2)(1,3); (1,0)(1,1) mirror of (0,2)(0,3)
            MMAF(acc[0], ah[0], bh[0]);
            MMAF(acc[1], ah[0], bh[1]);
            MMAF(acc[2], ah[0], bh[2]);
            MMAF(acc[3], ah[0], bh[3]);
            MMAF(acc[4], ah[1], bh[2]);
            MMAF(acc[5], ah[1], bh[3]);
        }
        __syncthreads();
    }

    // --- writeout partial Gram (mirror upper-right tiles to lower-left)
    float* P = g_Gp + ((size_t)ks * NB_ + n0 + w) * RSQ_;
    const int mt_of[6] = {0, 0, 0, 0, 1, 1};
    const int nt_of[6] = {0, 1, 2, 3, 2, 3};
#pragma unroll
    for (int ti = 0; ti < 6; ti++) {
        int r0 = mt_of[ti] * 16 + g;
        int r1 = r0 + 8;
        int q  = nt_of[ti] * 8 + tg2;
        P[r0 * 32 + q]     = acc[ti][0];
        P[r0 * 32 + q + 1] = acc[ti][1];
        P[r1 * 32 + q]     = acc[ti][2];
        P[r1 * 32 + q + 1] = acc[ti][3];
        if (ti == 2 || ti == 3) {
            P[q * 32 + r0]       = acc[ti][0];
            P[(q + 1) * 32 + r0] = acc[ti][1];
            P[q * 32 + r1]       = acc[ti][2];
            P[(q + 1) * 32 + r1] = acc[ti][3];
        }
    }
}

// sum K-split partials (float4 per thread)
__global__ void k_gsum() {
    int i4 = blockIdx.x * 256 + threadIdx.x;   // over 512*1024/4 float4s
    float4 s = {0.f, 0.f, 0.f, 0.f};
#pragma unroll
    for (int p = 0; p < KS_; p++) {
        float4 v = *((const float4*)(g_Gp + (size_t)p * NB_ * RSQ_) + i4);
        s.x += v.x; s.y += v.y; s.z += v.z; s.w += v.w;
    }
    *((float4*)g_G + i4) = s;
}

// ---------------------------------------------------------------- projection
__global__ void __launch_bounds__(256) k_proj(const float* __restrict__ projw) {
    __shared__ float sw[64][33];
    __shared__ float sf[16][33];
    int ot  = blockIdx.x;
    int kc  = blockIdx.y;
    int tid = threadIdx.x;
    int o0  = ot * 64;
    int b   = tid >> 4;
    int oo  = tid & 15;

    float acc[4] = {0.f, 0.f, 0.f, 0.f};

    for (int kt = 0; kt < KCLP_; kt += 32) {
        int kbase = kc * KCLP_ + kt;
        {
            int orow = tid >> 2;
            int part = tid & 3;
            const float4* src = (const float4*)(projw + (size_t)(o0 + orow) * KK_ + kbase + part * 8);
            float4 v0 = src[0], v1 = src[1];
            float* drow = &sw[orow][part * 8];
            drow[0] = v0.x; drow[1] = v0.y; drow[2] = v0.z; drow[3] = v0.w;
            drow[4] = v1.x; drow[5] = v1.y; drow[6] = v1.z; drow[7] = v1.w;
        }
        {
            int frow = tid >> 4;
            int fcol = (tid & 15) * 2;
            float2 v = *(const float2*)(g_G + (size_t)frow * KK_ + kbase + fcol);
            sf[frow][fcol]     = v.x;
            sf[frow][fcol + 1] = v.y;
        }
        __syncthreads();
#pragma unroll
        for (int k = 0; k < 32; k++) {
            float fv = sf[b][k];
            acc[0] += fv * sw[oo * 4 + 0][k];
            acc[1] += fv * sw[oo * 4 + 1][k];
            acc[2] += fv * sw[oo * 4 + 2][k];
            acc[3] += fv * sw[oo * 4 + 3][k];
        }
        __syncthreads();
    }
#pragma unroll
    for (int j = 0; j < 4; j++)
        g_part[(size_t)kc * (BB_ * OUT_) + b * OUT_ + o0 + oo * 4 + j] = acc[j];
}

__global__ void k_final(const float* __restrict__ projb, float* __restrict__ out) {
    int idx = blockIdx.x * blockDim.x + threadIdx.x;
    if (idx >= BB_ * OUT_) return;
    float s = projb[idx & (OUT_ - 1)];
#pragma unroll
    for (int kc = 0; kc < KCP_; kc++) s += g_part[kc * (BB_ * OUT_) + idx];
    out[idx] = s;
}

// ---------------------------------------------------------------- launch
extern "C" void kernel_launch(void* const* d_in, const int* in_sizes, int n_in,
                              void* d_out, int out_size) {
    const float* x     = (const float*)d_in[0];
    const float* core1 = (const float*)d_in[1];
    const float* core2 = (const float*)d_in[2];
    const float* core3 = (const float*)d_in[3];
    const float* projw = (const float*)d_in[4];
    const float* projb = (const float*)d_in[5];
    float* out = (float*)d_out;

    k_t<<<(HW_ * RS_ + 255) / 256, 256>>>(core2, core3);
    dim3 tg(JJ_ / 256, RS_);
    k_ttr<<<tg, 256>>>(core1);
    dim3 gg(NB_ / 8, KS_);
    k_gram<<<gg, 256>>>(x);
    k_gsum<<<(NB_ * RSQ_) / 1024, 256>>>();
    dim3 pg(16, KCP_);
    k_proj<<<pg, 256>>>(projw);
    k_final<<<(BB_ * OUT_ + 255) / 256, 256>>>(projb, out);
}